// round 6
// baseline (speedup 1.0000x reference)
#include <cuda_runtime.h>

#define POOLED 7
#define KSIZE  2
#define CROP   (POOLED * KSIZE)   // 14
#define HH     50
#define WW     50
#define CC     512
#define C4     (CC / 4)           // 128 16-byte groups per pixel
#define NROI   256

typedef unsigned long long u64;

// ---- packed f32x2 helpers (sm_103a) ----
__device__ __forceinline__ u64 pack2(float v) {
    u64 r; asm("mov.b64 %0, {%1, %1};" : "=l"(r) : "f"(v)); return r;
}
__device__ __forceinline__ u64 mul2(u64 a, u64 b) {
    u64 r; asm("mul.rn.f32x2 %0, %1, %2;" : "=l"(r) : "l"(a), "l"(b)); return r;
}
__device__ __forceinline__ u64 fma2(u64 a, u64 b, u64 c) {
    u64 r; asm("fma.rn.f32x2 %0, %1, %2, %3;" : "=l"(r) : "l"(a), "l"(b), "l"(c)); return r;
}
__device__ __forceinline__ void unpack2(u64 v, float& lo, float& hi) {
    asm("mov.b64 {%0, %1}, %2;" : "=f"(lo), "=f"(hi) : "l"(v));
}
// lerp(a,b,w) = a*uw + b*w, with uw = (1-w) premasked by validity
__device__ __forceinline__ u64 lerp2(u64 a, u64 b, u64 uw, u64 w) {
    return fma2(a, uw, mul2(b, w));
}

__global__ void __launch_bounds__(128, 10)
roi_pool_kernel(const float* __restrict__ fm,
                const float* __restrict__ rois,
                float* __restrict__ out) {
    const int blk = blockIdx.x;             // 0 .. 256*7-1 = n*7 + ph
    const int n  = blk / POOLED;
    const int ph = blk - n * POOLED;
    const int b  = n >> 7;

    // rois flat: n*4 + {0:x1, 1:y1, 2:x2, 3:y2} (after reference's [1,0,3,2] perm)
    const float4 rr = __ldg((const float4*)rois + n);
    const float sy = (rr.w - rr.y) * (float)(HH - 1) / (float)(CROP - 1);
    const float sx = (rr.z - rr.x) * (float)(WW - 1) / (float)(CROP - 1);
    const float by = rr.y * (float)(HH - 1);
    const float bx = rr.x * (float)(WW - 1);

    // ---- per-(n,ph) y setup, amortized over 7 pw cells ----
    int y0i[KSIZE], y1i[KSIZE];
    u64 wy2[KSIZE], uy2[KSIZE];
#pragma unroll
    for (int ky = 0; ky < KSIZE; ky++) {
        const float i  = (float)(KSIZE * ph + ky);
        const float ys = by + i * sy;
        const float m  = ((ys >= 0.0f) && (ys <= (float)(HH - 1))) ? 1.0f : 0.0f;
        const float y0f = floorf(ys);
        const float w   = ys - y0f;
        wy2[ky] = pack2(w * m);
        uy2[ky] = pack2((1.0f - w) * m);
        int y0 = (int)y0f;
        y0 = min(max(y0, 0), HH - 1);
        y0i[ky] = y0;
        y1i[ky] = min(y0 + 1, HH - 1);
    }

    const int c4 = threadIdx.x;
    const ulonglong2* __restrict__ base =
        (const ulonglong2*)fm + b * (HH * WW * C4) + c4;
    // 4 row pointers, hoisted out of the pw loop
    const ulonglong2* __restrict__ R0 = base + y0i[0] * (WW * C4);
    const ulonglong2* __restrict__ R1 = base + y1i[0] * (WW * C4);
    const ulonglong2* __restrict__ R2 = base + y0i[1] * (WW * C4);
    const ulonglong2* __restrict__ R3 = base + y1i[1] * (WW * C4);

    float4* __restrict__ outp =
        (float4*)out + (blk * POOLED) * C4 + c4;

    // Fully unrolled pw loop: ptxas software-pipelines the 16 LDG.128 of
    // iteration pw+1 into the FMA window of iteration pw.
#pragma unroll
    for (int pw = 0; pw < POOLED; pw++) {
        // ---- per-pw x setup (validity folded into packed weights) ----
        int o0, o1, o2, o3;
        u64 wx2[KSIZE], ux2[KSIZE];
        {
            const float j  = (float)(KSIZE * pw);
            const float xs = bx + j * sx;
            const float m  = ((xs >= 0.0f) && (xs <= (float)(WW - 1))) ? 1.0f : 0.0f;
            const float x0f = floorf(xs);
            const float w   = xs - x0f;
            wx2[0] = pack2(w * m);
            ux2[0] = pack2((1.0f - w) * m);
            int x0 = (int)x0f;
            x0 = min(max(x0, 0), WW - 1);
            o0 = x0 * C4;
            o1 = min(x0 + 1, WW - 1) * C4;
        }
        {
            const float j  = (float)(KSIZE * pw + 1);
            const float xs = bx + j * sx;
            const float m  = ((xs >= 0.0f) && (xs <= (float)(WW - 1))) ? 1.0f : 0.0f;
            const float x0f = floorf(xs);
            const float w   = xs - x0f;
            wx2[1] = pack2(w * m);
            ux2[1] = pack2((1.0f - w) * m);
            int x0 = (int)x0f;
            x0 = min(max(x0, 0), WW - 1);
            o2 = x0 * C4;
            o3 = min(x0 + 1, WW - 1) * C4;
        }

        // ---- 16 independent 16B loads ----
        ulonglong2 p00 = R0[o0];
        ulonglong2 p01 = R0[o1];
        ulonglong2 p02 = R0[o2];
        ulonglong2 p03 = R0[o3];
        ulonglong2 p10 = R1[o0];
        ulonglong2 p11 = R1[o1];
        ulonglong2 p12 = R1[o2];
        ulonglong2 p13 = R1[o3];
        ulonglong2 p20 = R2[o0];
        ulonglong2 p21 = R2[o1];
        ulonglong2 p22 = R2[o2];
        ulonglong2 p23 = R2[o3];
        ulonglong2 p30 = R3[o0];
        ulonglong2 p31 = R3[o1];
        ulonglong2 p32 = R3[o2];
        ulonglong2 p33 = R3[o3];

        float b0 = -__FLT_MAX__, b1 = -__FLT_MAX__,
              b2 = -__FLT_MAX__, b3 = -__FLT_MAX__;

        {   // ky0 kx0
            u64 t0l = lerp2(p00.x, p10.x, uy2[0], wy2[0]);
            u64 t0h = lerp2(p00.y, p10.y, uy2[0], wy2[0]);
            u64 t1l = lerp2(p01.x, p11.x, uy2[0], wy2[0]);
            u64 t1h = lerp2(p01.y, p11.y, uy2[0], wy2[0]);
            u64 vl  = lerp2(t0l, t1l, ux2[0], wx2[0]);
            u64 vh  = lerp2(t0h, t1h, ux2[0], wx2[0]);
            float f0, f1, f2, f3;
            unpack2(vl, f0, f1); unpack2(vh, f2, f3);
            b0 = fmaxf(b0, f0); b1 = fmaxf(b1, f1);
            b2 = fmaxf(b2, f2); b3 = fmaxf(b3, f3);
        }
        {   // ky0 kx1
            u64 t0l = lerp2(p02.x, p12.x, uy2[0], wy2[0]);
            u64 t0h = lerp2(p02.y, p12.y, uy2[0], wy2[0]);
            u64 t1l = lerp2(p03.x, p13.x, uy2[0], wy2[0]);
            u64 t1h = lerp2(p03.y, p13.y, uy2[0], wy2[0]);
            u64 vl  = lerp2(t0l, t1l, ux2[1], wx2[1]);
            u64 vh  = lerp2(t0h, t1h, ux2[1], wx2[1]);
            float f0, f1, f2, f3;
            unpack2(vl, f0, f1); unpack2(vh, f2, f3);
            b0 = fmaxf(b0, f0); b1 = fmaxf(b1, f1);
            b2 = fmaxf(b2, f2); b3 = fmaxf(b3, f3);
        }
        {   // ky1 kx0
            u64 t0l = lerp2(p20.x, p30.x, uy2[1], wy2[1]);
            u64 t0h = lerp2(p20.y, p30.y, uy2[1], wy2[1]);
            u64 t1l = lerp2(p21.x, p31.x, uy2[1], wy2[1]);
            u64 t1h = lerp2(p21.y, p31.y, uy2[1], wy2[1]);
            u64 vl  = lerp2(t0l, t1l, ux2[0], wx2[0]);
            u64 vh  = lerp2(t0h, t1h, ux2[0], wx2[0]);
            float f0, f1, f2, f3;
            unpack2(vl, f0, f1); unpack2(vh, f2, f3);
            b0 = fmaxf(b0, f0); b1 = fmaxf(b1, f1);
            b2 = fmaxf(b2, f2); b3 = fmaxf(b3, f3);
        }
        {   // ky1 kx1
            u64 t0l = lerp2(p22.x, p32.x, uy2[1], wy2[1]);
            u64 t0h = lerp2(p22.y, p32.y, uy2[1], wy2[1]);
            u64 t1l = lerp2(p23.x, p33.x, uy2[1], wy2[1]);
            u64 t1h = lerp2(p23.y, p33.y, uy2[1], wy2[1]);
            u64 vl  = lerp2(t0l, t1l, ux2[1], wx2[1]);
            u64 vh  = lerp2(t0h, t1h, ux2[1], wx2[1]);
            float f0, f1, f2, f3;
            unpack2(vl, f0, f1); unpack2(vh, f2, f3);
            b0 = fmaxf(b0, f0); b1 = fmaxf(b1, f1);
            b2 = fmaxf(b2, f2); b3 = fmaxf(b3, f3);
        }

        float4 res;
        res.x = b0; res.y = b1; res.z = b2; res.w = b3;
        outp[pw * C4] = res;
    }
}

extern "C" void kernel_launch(void* const* d_in, const int* in_sizes, int n_in,
                              void* d_out, int out_size) {
    const float* fm   = (const float*)d_in[0];   // (2,50,50,512) f32
    const float* rois = (const float*)d_in[1];   // (2,128,4) f32
    float* out = (float*)d_out;                  // (256,7,7,512) f32

    const int blocks = NROI * POOLED;            // 1792
    roi_pool_kernel<<<blocks, 128>>>(fm, rois, out);
}

// round 7
// speedup vs baseline: 1.1931x; 1.1931x over previous
#include <cuda_runtime.h>

#define POOLED 7
#define KSIZE  2
#define CROP   (POOLED * KSIZE)   // 14
#define HH     50
#define WW     50
#define CC     512
#define C4     (CC / 4)           // 128 16-byte groups per pixel
#define NROI   256

typedef unsigned long long u64;

// ---- packed f32x2 helpers (sm_103a) ----
__device__ __forceinline__ u64 pack2(float v) {
    u64 r; asm("mov.b64 %0, {%1, %1};" : "=l"(r) : "f"(v)); return r;
}
__device__ __forceinline__ u64 mul2(u64 a, u64 b) {
    u64 r; asm("mul.rn.f32x2 %0, %1, %2;" : "=l"(r) : "l"(a), "l"(b)); return r;
}
__device__ __forceinline__ u64 fma2(u64 a, u64 b, u64 c) {
    u64 r; asm("fma.rn.f32x2 %0, %1, %2, %3;" : "=l"(r) : "l"(a), "l"(b), "l"(c)); return r;
}
__device__ __forceinline__ void unpack2(u64 v, float& lo, float& hi) {
    asm("mov.b64 {%0, %1}, %2;" : "=f"(lo), "=f"(hi) : "l"(v));
}
// lerp(a,b,w) = a*uw + b*w, with uw = (1-w) premasked by validity
__device__ __forceinline__ u64 lerp2(u64 a, u64 b, u64 uw, u64 w) {
    return fma2(a, uw, mul2(b, w));
}

__global__ void __launch_bounds__(128, 12)
roi_pool_kernel(const float* __restrict__ fm,
                const float* __restrict__ rois,
                float* __restrict__ out) {
    const int blk = blockIdx.x;             // 0 .. 256*7-1 = n*7 + ph
    const int n  = blk / POOLED;
    const int ph = blk - n * POOLED;
    const int b  = n >> 7;

    // rois flat: n*4 + {0:x1, 1:y1, 2:x2, 3:y2} (after reference's [1,0,3,2] perm)
    const float4 rr = __ldg((const float4*)rois + n);
    const float sy = (rr.w - rr.y) * (float)(HH - 1) / (float)(CROP - 1);
    const float sx = (rr.z - rr.x) * (float)(WW - 1) / (float)(CROP - 1);
    const float by = rr.y * (float)(HH - 1);
    const float bx = rr.x * (float)(WW - 1);

    // ---- per-(n,ph) y setup, amortized over 7 pw cells ----
    int y0i[KSIZE], y1i[KSIZE];
    u64 wy2[KSIZE], uy2[KSIZE];
#pragma unroll
    for (int ky = 0; ky < KSIZE; ky++) {
        const float i  = (float)(KSIZE * ph + ky);
        const float ys = by + i * sy;
        const float m  = ((ys >= 0.0f) && (ys <= (float)(HH - 1))) ? 1.0f : 0.0f;
        const float y0f = floorf(ys);
        const float w   = ys - y0f;
        wy2[ky] = pack2(w * m);
        uy2[ky] = pack2((1.0f - w) * m);
        int y0 = (int)y0f;
        y0 = min(max(y0, 0), HH - 1);
        y0i[ky] = y0;
        y1i[ky] = min(y0 + 1, HH - 1);
    }

    const int c4 = threadIdx.x;
    const ulonglong2* __restrict__ base =
        (const ulonglong2*)fm + b * (HH * WW * C4) + c4;
    // 4 row pointers, hoisted out of the pw loop
    const ulonglong2* __restrict__ R0 = base + y0i[0] * (WW * C4);
    const ulonglong2* __restrict__ R1 = base + y1i[0] * (WW * C4);
    const ulonglong2* __restrict__ R2 = base + y0i[1] * (WW * C4);
    const ulonglong2* __restrict__ R3 = base + y1i[1] * (WW * C4);

    float4* __restrict__ outp =
        (float4*)out + (blk * POOLED) * C4 + c4;

#pragma unroll 1
    for (int pw = 0; pw < POOLED; pw++) {
        // ---- per-pw x setup (validity folded into packed weights) ----
        int o0, o1, o2, o3;
        u64 wx2[KSIZE], ux2[KSIZE];
        {
            const float j  = (float)(KSIZE * pw);
            const float xs = bx + j * sx;
            const float m  = ((xs >= 0.0f) && (xs <= (float)(WW - 1))) ? 1.0f : 0.0f;
            const float x0f = floorf(xs);
            const float w   = xs - x0f;
            wx2[0] = pack2(w * m);
            ux2[0] = pack2((1.0f - w) * m);
            int x0 = (int)x0f;
            x0 = min(max(x0, 0), WW - 1);
            o0 = x0 * C4;
            o1 = min(x0 + 1, WW - 1) * C4;
        }
        {
            const float j  = (float)(KSIZE * pw + 1);
            const float xs = bx + j * sx;
            const float m  = ((xs >= 0.0f) && (xs <= (float)(WW - 1))) ? 1.0f : 0.0f;
            const float x0f = floorf(xs);
            const float w   = xs - x0f;
            wx2[1] = pack2(w * m);
            ux2[1] = pack2((1.0f - w) * m);
            int x0 = (int)x0f;
            x0 = min(max(x0, 0), WW - 1);
            o2 = x0 * C4;
            o3 = min(x0 + 1, WW - 1) * C4;
        }

        // ---- 16 independent 16B loads, all up front ----
        ulonglong2 p00 = R0[o0];
        ulonglong2 p01 = R0[o1];
        ulonglong2 p02 = R0[o2];
        ulonglong2 p03 = R0[o3];
        ulonglong2 p10 = R1[o0];
        ulonglong2 p11 = R1[o1];
        ulonglong2 p12 = R1[o2];
        ulonglong2 p13 = R1[o3];
        ulonglong2 p20 = R2[o0];
        ulonglong2 p21 = R2[o1];
        ulonglong2 p22 = R2[o2];
        ulonglong2 p23 = R2[o3];
        ulonglong2 p30 = R3[o0];
        ulonglong2 p31 = R3[o1];
        ulonglong2 p32 = R3[o2];
        ulonglong2 p33 = R3[o3];

        float b0 = -__FLT_MAX__, b1 = -__FLT_MAX__,
              b2 = -__FLT_MAX__, b3 = -__FLT_MAX__;

        {   // ky0 kx0
            u64 t0l = lerp2(p00.x, p10.x, uy2[0], wy2[0]);
            u64 t0h = lerp2(p00.y, p10.y, uy2[0], wy2[0]);
            u64 t1l = lerp2(p01.x, p11.x, uy2[0], wy2[0]);
            u64 t1h = lerp2(p01.y, p11.y, uy2[0], wy2[0]);
            u64 vl  = lerp2(t0l, t1l, ux2[0], wx2[0]);
            u64 vh  = lerp2(t0h, t1h, ux2[0], wx2[0]);
            float f0, f1, f2, f3;
            unpack2(vl, f0, f1); unpack2(vh, f2, f3);
            b0 = fmaxf(b0, f0); b1 = fmaxf(b1, f1);
            b2 = fmaxf(b2, f2); b3 = fmaxf(b3, f3);
        }
        {   // ky0 kx1
            u64 t0l = lerp2(p02.x, p12.x, uy2[0], wy2[0]);
            u64 t0h = lerp2(p02.y, p12.y, uy2[0], wy2[0]);
            u64 t1l = lerp2(p03.x, p13.x, uy2[0], wy2[0]);
            u64 t1h = lerp2(p03.y, p13.y, uy2[0], wy2[0]);
            u64 vl  = lerp2(t0l, t1l, ux2[1], wx2[1]);
            u64 vh  = lerp2(t0h, t1h, ux2[1], wx2[1]);
            float f0, f1, f2, f3;
            unpack2(vl, f0, f1); unpack2(vh, f2, f3);
            b0 = fmaxf(b0, f0); b1 = fmaxf(b1, f1);
            b2 = fmaxf(b2, f2); b3 = fmaxf(b3, f3);
        }
        {   // ky1 kx0
            u64 t0l = lerp2(p20.x, p30.x, uy2[1], wy2[1]);
            u64 t0h = lerp2(p20.y, p30.y, uy2[1], wy2[1]);
            u64 t1l = lerp2(p21.x, p31.x, uy2[1], wy2[1]);
            u64 t1h = lerp2(p21.y, p31.y, uy2[1], wy2[1]);
            u64 vl  = lerp2(t0l, t1l, ux2[0], wx2[0]);
            u64 vh  = lerp2(t0h, t1h, ux2[0], wx2[0]);
            float f0, f1, f2, f3;
            unpack2(vl, f0, f1); unpack2(vh, f2, f3);
            b0 = fmaxf(b0, f0); b1 = fmaxf(b1, f1);
            b2 = fmaxf(b2, f2); b3 = fmaxf(b3, f3);
        }
        {   // ky1 kx1
            u64 t0l = lerp2(p22.x, p32.x, uy2[1], wy2[1]);
            u64 t0h = lerp2(p22.y, p32.y, uy2[1], wy2[1]);
            u64 t1l = lerp2(p23.x, p33.x, uy2[1], wy2[1]);
            u64 t1h = lerp2(p23.y, p33.y, uy2[1], wy2[1]);
            u64 vl  = lerp2(t0l, t1l, ux2[1], wx2[1]);
            u64 vh  = lerp2(t0h, t1h, ux2[1], wx2[1]);
            float f0, f1, f2, f3;
            unpack2(vl, f0, f1); unpack2(vh, f2, f3);
            b0 = fmaxf(b0, f0); b1 = fmaxf(b1, f1);
            b2 = fmaxf(b2, f2); b3 = fmaxf(b3, f3);
        }

        float4 res;
        res.x = b0; res.y = b1; res.z = b2; res.w = b3;
        outp[pw * C4] = res;
    }
}

extern "C" void kernel_launch(void* const* d_in, const int* in_sizes, int n_in,
                              void* d_out, int out_size) {
    const float* fm   = (const float*)d_in[0];   // (2,50,50,512) f32
    const float* rois = (const float*)d_in[1];   // (2,128,4) f32
    float* out = (float*)d_out;                  // (256,7,7,512) f32

    const int blocks = NROI * POOLED;            // 1792
    roi_pool_kernel<<<blocks, 128>>>(fm, rois, out);
}